// round 14
// baseline (speedup 1.0000x reference)
#include <cuda_runtime.h>
#include <math.h>
#include <stdint.h>

#define BATCH 8
#define NPTS  4096
#define KNN   16
#define CH    64
#define NTILE 16
#define SAMP  256            // NTILE * KNN samples per tile block
#define NBLK  2048           // BATCH * (NPTS / NTILE)
#define GPAD  68             // padded row length for [s][c] smem tiles

// ---------------- device scratch (no allocations allowed) ----------------
__device__ float  g_rel[BATCH * NPTS * KNN * 3];        // 6.3 MB relative vectors
__device__ float  g_h1[(size_t)NBLK * SAMP * CH];       // 134 MB h1, layout [block][s][o]
__device__ double g_mom[9];                             // rel moments
__device__ float  g_w1f[CH * 3];                        // BN0-folded w1
__device__ float  g_b1f[CH];
__device__ double g_s1[CH];                             // sum h1 per channel
__device__ double g_ss1[CH];                            // sum h1^2 per channel
__device__ float  g_a1[CH];                             // BN1 scale
__device__ float  g_c1[CH];                             // BN1 shift

// ---------------- tf32 helpers ----------------
__device__ __forceinline__ uint32_t f2tf32(float x) {
    uint32_t r;
    asm("cvt.rna.tf32.f32 %0, %1;" : "=r"(r) : "f"(x));
    return r;
}
__device__ __forceinline__ void tf32_split(float x, uint32_t& hi, uint32_t& lo) {
    hi = f2tf32(x);
    float rem = x - __uint_as_float(hi);
    lo = f2tf32(rem);
}
__device__ __forceinline__ void mma_tf32(float& c0, float& c1, float& c2, float& c3,
                                         uint32_t a0, uint32_t a1, uint32_t a2, uint32_t a3,
                                         uint32_t b0, uint32_t b1) {
    asm("mma.sync.aligned.m16n8k8.row.col.f32.tf32.tf32.f32 "
        "{%0,%1,%2,%3}, {%4,%5,%6,%7}, {%8,%9}, {%0,%1,%2,%3};"
        : "+f"(c0), "+f"(c1), "+f"(c2), "+f"(c3)
        : "r"(a0), "r"(a1), "r"(a2), "r"(a3), "r"(b0), "r"(b1));
}

// ---------------- K0: zero the cross-launch accumulators ----------------
__global__ void k0_init() {
    int t = threadIdx.x;
    if (t < 9)  g_mom[t] = 0.0;
    if (t < CH) { g_s1[t] = 0.0; g_ss1[t] = 0.0; }
}

// ---------------- K1: KNN (ranks 2..17 by LARGEST distance) + rel + rel moments ----
__global__ __launch_bounds__(256) void k1_knn(const float* __restrict__ xyz) {
    extern __shared__ float4 pts[];      // 4096 x (x,y,z,|p|^2) = 64 KB
    __shared__ float sacc[9];
    const int t    = threadIdx.x;
    const int b    = blockIdx.x >> 4;
    const int tile = blockIdx.x & 15;
    const float* xb = xyz + (size_t)b * 3 * NPTS;
    for (int n = t; n < NPTS; n += 256) {
        float x = xb[n], y = xb[NPTS + n], z = xb[2 * NPTS + n];
        pts[n] = make_float4(x, y, z, fmaf(x, x, fmaf(y, y, z * z)));
    }
    if (t < 9) sacc[t] = 0.0f;
    __syncthreads();

    const int i = tile * 256 + t;
    const float4 q = pts[i];

    float bd[17]; int bi[17];
    #pragma unroll
    for (int u = 0; u < 17; ++u) { bd[u] = -1e30f; bi[u] = 0; }
    float cmin = -1e30f; int cpos = 0;

    #pragma unroll 4
    for (int j = 0; j < NPTS; ++j) {
        float4 p = pts[j];
        float dt = fmaf(q.x, p.x, fmaf(q.y, p.y, q.z * p.z));
        float d  = q.w + p.w - 2.0f * dt;
        if (d > cmin) {            // strict >: ties keep earlier (lower) index, like jax top_k
            bd[cpos] = d; bi[cpos] = j;
            cmin = bd[0]; cpos = 0;
            #pragma unroll
            for (int u = 1; u < 17; ++u)
                if (bd[u] < cmin) { cmin = bd[u]; cpos = u; }
        }
    }

    float mval = bd[0]; int mpos = 0;
    #pragma unroll
    for (int u = 1; u < 17; ++u)
        if (bd[u] > mval || (bd[u] == mval && bi[u] < bi[mpos])) { mval = bd[u]; mpos = u; }

    float sx=0,sy=0,sz=0,sxx=0,sxy=0,sxz=0,syy=0,syz=0,szz=0;
    float* outr = g_rel + (size_t)(b * NPTS + i) * (KNN * 3);
    int kk = 0;
    #pragma unroll
    for (int u = 0; u < 17; ++u) {
        if (u == mpos) continue;
        float4 p = pts[bi[u]];
        float rx = p.x - q.x, ry = p.y - q.y, rz = p.z - q.z;
        outr[kk*3+0] = rx; outr[kk*3+1] = ry; outr[kk*3+2] = rz;
        ++kk;
        sx += rx; sy += ry; sz += rz;
        sxx = fmaf(rx,rx,sxx); sxy = fmaf(rx,ry,sxy); sxz = fmaf(rx,rz,sxz);
        syy = fmaf(ry,ry,syy); syz = fmaf(ry,rz,syz); szz = fmaf(rz,rz,szz);
    }
    atomicAdd(&sacc[0],sx);  atomicAdd(&sacc[1],sy);  atomicAdd(&sacc[2],sz);
    atomicAdd(&sacc[3],sxx); atomicAdd(&sacc[4],sxy); atomicAdd(&sacc[5],sxz);
    atomicAdd(&sacc[6],syy); atomicAdd(&sacc[7],syz); atomicAdd(&sacc[8],szz);
    __syncthreads();
    if (t < 9) atomicAdd(&g_mom[t], (double)sacc[t]);
}

// ---------------- K2: fold block-0 BN into w1 (exact, from rel moments) ----------------
__global__ void k2_fold0(const float* __restrict__ w1, const float* __restrict__ b1,
                         const float* __restrict__ gamma, const float* __restrict__ beta) {
    int o = threadIdx.x;
    if (o >= CH) return;
    double inv = 1.0 / ((double)BATCH * NPTS * KNN);
    double m0=g_mom[0]*inv, m1=g_mom[1]*inv, m2=g_mom[2]*inv;
    double Mxx=g_mom[3]*inv, Mxy=g_mom[4]*inv, Mxz=g_mom[5]*inv;
    double Myy=g_mom[6]*inv, Myz=g_mom[7]*inv, Mzz=g_mom[8]*inv;
    double wx=w1[o*3+0], wy=w1[o*3+1], wz=w1[o*3+2], bb=b1[o];
    double wm = wx*m0 + wy*m1 + wz*m2;
    double mu = wm + bb;
    double e2 = wx*wx*Mxx + wy*wy*Myy + wz*wz*Mzz
              + 2.0*(wx*wy*Mxy + wx*wz*Mxz + wy*wz*Myz)
              + 2.0*bb*wm + bb*bb;
    double var = e2 - mu*mu;
    double a = (double)gamma[o] / sqrt(var + 1e-5);
    g_w1f[o*3+0]=(float)(a*wx); g_w1f[o*3+1]=(float)(a*wy); g_w1f[o*3+2]=(float)(a*wz);
    g_b1f[o]=(float)(a*(bb-mu) + (double)beta[o]);
}

// ---------------- K3: g1 = relu(BN0(w1 rel)); h1 = w2 g1 + b2 (tf32 MMA, pre-split B) ----
__global__ __launch_bounds__(512, 1) void k3_h1(const float* __restrict__ w2, const float* __restrict__ b2) {
    extern __shared__ uint32_t smu[];
    uint32_t* ghi = smu;                       // [256][GPAD]  (69632 B)
    uint32_t* glo = smu + SAMP*GPAD;           // [256][GPAD]  (69632 B)
    float*    w2s = (float*)(smu + 2*SAMP*GPAD); // [64][64]    (16384 B)
    __shared__ float w1fs[CH*3], b1fs[CH], b2s[CH], sh1[CH], sq1[CH];
    const int t  = threadIdx.x;
    const int b  = blockIdx.x >> 8;
    const int n0blk = (blockIdx.x & 255) * NTILE;

    for (int idx = t; idx < CH*CH; idx += 512) w2s[idx] = w2[idx];
    if (t < CH*3) w1fs[t] = g_w1f[t];
    if (t < CH) { b1fs[t] = g_b1f[t]; b2s[t] = b2[t]; sh1[t]=0.f; sq1[t]=0.f; }
    __syncthreads();

    {   // stage 1: g1 for this tile; thread -> (sample s = t>>1, ch half (t&1)*32)
        const int s = t >> 1, ch0 = (t & 1) * 32;
        const int nl = s >> 4, k = s & 15;
        const float* r = g_rel + (size_t)((b*NPTS + n0blk + nl)*KNN + k)*3;
        float rx=r[0], ry=r[1], rz=r[2];
        uint32_t* rh = ghi + s*GPAD;
        uint32_t* rl = glo + s*GPAD;
        #pragma unroll 8
        for (int o = ch0; o < ch0+32; ++o) {
            float h = fmaxf(fmaf(w1fs[o*3], rx, fmaf(w1fs[o*3+1], ry, fmaf(w1fs[o*3+2], rz, b1fs[o]))), 0.f);
            uint32_t hi, lo; tf32_split(h, hi, lo);
            rh[o] = hi; rl[o] = lo;
        }
    }
    __syncthreads();

    // mma stage: 16 warps = m-tile (warp&3) x sample-quarter (warp>>2, 64 samples)
    const int warp = t >> 5, lane = t & 31, lr = lane >> 2, lc = lane & 3;
    const int m0 = (warp & 3) * 16, sq = warp >> 2;

    uint32_t ahi[8][4], alo[8][4];
    #pragma unroll
    for (int kk = 0; kk < 8; ++kk) {
        int c0i = kk*8 + lc;
        tf32_split(w2s[(m0+lr  )*CH + c0i    ], ahi[kk][0], alo[kk][0]);
        tf32_split(w2s[(m0+lr+8)*CH + c0i    ], ahi[kk][1], alo[kk][1]);
        tf32_split(w2s[(m0+lr  )*CH + c0i + 4], ahi[kk][2], alo[kk][2]);
        tf32_split(w2s[(m0+lr+8)*CH + c0i + 4], ahi[kk][3], alo[kk][3]);
    }

    float bias0 = b2s[m0+lr], bias1 = b2s[m0+8+lr];
    float sum0=0.f, ssq0=0.f, sum1=0.f, ssq1=0.f;
    float* hb = g_h1 + (size_t)blockIdx.x * (SAMP*CH);

    for (int nt = 0; nt < 8; ++nt) {
        const int n0 = sq*64 + nt*8;
        float h0=bias0,h1=bias0,h2=bias1,h3=bias1;   // Ahi*Bhi (+bias)
        float m0a=0,m1a=0,m2a=0,m3a=0;               // Ahi*Blo
        float l0=0,l1=0,l2=0,l3=0;                   // Alo*Bhi
        const uint32_t* rh = ghi + (n0+lr)*GPAD;
        const uint32_t* rl = glo + (n0+lr)*GPAD;
        #pragma unroll
        for (int kk = 0; kk < 8; ++kk) {
            uint32_t bh0 = rh[kk*8 + lc], bh1 = rh[kk*8 + lc + 4];
            uint32_t bl0 = rl[kk*8 + lc], bl1 = rl[kk*8 + lc + 4];
            mma_tf32(h0,h1,h2,h3, ahi[kk][0],ahi[kk][1],ahi[kk][2],ahi[kk][3], bh0,bh1);
            mma_tf32(m0a,m1a,m2a,m3a, ahi[kk][0],ahi[kk][1],ahi[kk][2],ahi[kk][3], bl0,bl1);
            mma_tf32(l0,l1,l2,l3, alo[kk][0],alo[kk][1],alo[kk][2],alo[kk][3], bh0,bh1);
        }
        float c0 = h0 + (m0a + l0);
        float c1 = h1 + (m1a + l1);
        float c2 = h2 + (m2a + l2);
        float c3 = h3 + (m3a + l3);
        const int s0 = n0 + 2*lc;
        hb[(s0  )*CH + m0+lr  ] = c0;
        hb[(s0+1)*CH + m0+lr  ] = c1;
        hb[(s0  )*CH + m0+8+lr] = c2;
        hb[(s0+1)*CH + m0+8+lr] = c3;
        sum0 += c0 + c1;  ssq0 = fmaf(c0,c0, fmaf(c1,c1, ssq0));
        sum1 += c2 + c3;  ssq1 = fmaf(c2,c2, fmaf(c3,c3, ssq1));
    }
    sum0 += __shfl_xor_sync(0xFFFFFFFFu, sum0, 1); sum0 += __shfl_xor_sync(0xFFFFFFFFu, sum0, 2);
    ssq0 += __shfl_xor_sync(0xFFFFFFFFu, ssq0, 1); ssq0 += __shfl_xor_sync(0xFFFFFFFFu, ssq0, 2);
    sum1 += __shfl_xor_sync(0xFFFFFFFFu, sum1, 1); sum1 += __shfl_xor_sync(0xFFFFFFFFu, sum1, 2);
    ssq1 += __shfl_xor_sync(0xFFFFFFFFu, ssq1, 1); ssq1 += __shfl_xor_sync(0xFFFFFFFFu, ssq1, 2);
    if (lc == 0) {
        atomicAdd(&sh1[m0+lr  ], sum0); atomicAdd(&sq1[m0+lr  ], ssq0);
        atomicAdd(&sh1[m0+8+lr], sum1); atomicAdd(&sq1[m0+8+lr], ssq1);
    }
    __syncthreads();
    if (t < CH) { atomicAdd(&g_s1[t], (double)sh1[t]); atomicAdd(&g_ss1[t], (double)sq1[t]); }
}

// ---------------- K3b: finalize block-1 BN affine ----------------
__global__ void k3b_fold1(const float* __restrict__ gamma, const float* __restrict__ beta) {
    int o = threadIdx.x;
    if (o >= CH) return;
    double inv = 1.0 / ((double)BATCH * NPTS * KNN);
    double mu  = g_s1[o] * inv;
    double var = g_ss1[o] * inv - mu*mu;
    double a = (double)gamma[o] / sqrt(var + 1e-5);
    g_a1[o] = (float)a;
    g_c1[o] = (float)((double)beta[o] - a*mu);
}

// ---------------- K4: g2 = relu(BN1(h1)); h2 = w2 g2 + b2; max over k -> out ----------------
__global__ __launch_bounds__(512, 1) void k4_out(const float* __restrict__ w2, const float* __restrict__ b2,
                                                  float* __restrict__ out) {
    extern __shared__ uint32_t smu[];
    uint32_t* ghi = smu;
    uint32_t* glo = smu + SAMP*GPAD;
    float*    w2s = (float*)(smu + 2*SAMP*GPAD);
    __shared__ __align__(16) float a1s[CH];
    __shared__ __align__(16) float c1s[CH];
    __shared__ float b2s[CH];
    const int t  = threadIdx.x;
    const int b  = blockIdx.x >> 8;
    const int n0blk = (blockIdx.x & 255) * NTILE;

    for (int idx = t; idx < CH*CH; idx += 512) w2s[idx] = w2[idx];
    if (t < CH) { a1s[t]=g_a1[t]; c1s[t]=g_c1[t]; b2s[t]=b2[t]; }
    __syncthreads();

    // BN + relu + split -> hi/lo tiles (h1 stored [s][o] -> coalesced)
    const float* hb = g_h1 + (size_t)blockIdx.x * (SAMP*CH);
    for (int idx = t*4; idx < SAMP*CH; idx += 512*4) {
        float4 v = *(const float4*)(hb + idx);
        int o = idx & 63, s = idx >> 6;
        float4 a = *(const float4*)(a1s + o);
        float4 c = *(const float4*)(c1s + o);
        v.x = fmaxf(fmaf(a.x, v.x, c.x), 0.f);
        v.y = fmaxf(fmaf(a.y, v.y, c.y), 0.f);
        v.z = fmaxf(fmaf(a.z, v.z, c.z), 0.f);
        v.w = fmaxf(fmaf(a.w, v.w, c.w), 0.f);
        uint32_t h0,l0,h1,l1,h2,l2,h3,l3;
        tf32_split(v.x, h0, l0); tf32_split(v.y, h1, l1);
        tf32_split(v.z, h2, l2); tf32_split(v.w, h3, l3);
        uint32_t* rh = ghi + s*GPAD + o;
        uint32_t* rl = glo + s*GPAD + o;
        rh[0]=h0; rh[1]=h1; rh[2]=h2; rh[3]=h3;
        rl[0]=l0; rl[1]=l1; rl[2]=l2; rl[3]=l3;
    }
    __syncthreads();

    const int warp = t >> 5, lane = t & 31, lr = lane >> 2, lc = lane & 3;
    const int m0 = (warp & 3) * 16, sq = warp >> 2;

    uint32_t ahi[8][4], alo[8][4];
    #pragma unroll
    for (int kk = 0; kk < 8; ++kk) {
        int c0i = kk*8 + lc;
        tf32_split(w2s[(m0+lr  )*CH + c0i    ], ahi[kk][0], alo[kk][0]);
        tf32_split(w2s[(m0+lr+8)*CH + c0i    ], ahi[kk][1], alo[kk][1]);
        tf32_split(w2s[(m0+lr  )*CH + c0i + 4], ahi[kk][2], alo[kk][2]);
        tf32_split(w2s[(m0+lr+8)*CH + c0i + 4], ahi[kk][3], alo[kk][3]);
    }

    float bias0 = b2s[m0+lr], bias1 = b2s[m0+8+lr];
    float prev0 = 0.f, prev1 = 0.f;

    for (int nt = 0; nt < 8; ++nt) {
        const int n0 = sq*64 + nt*8;
        float h0=bias0,h1=bias0,h2=bias1,h3=bias1;
        float m0a=0,m1a=0,m2a=0,m3a=0;
        float l0=0,l1=0,l2=0,l3=0;
        const uint32_t* rh = ghi + (n0+lr)*GPAD;
        const uint32_t* rl = glo + (n0+lr)*GPAD;
        #pragma unroll
        for (int kk = 0; kk < 8; ++kk) {
            uint32_t bh0 = rh[kk*8 + lc], bh1 = rh[kk*8 + lc + 4];
            uint32_t bl0 = rl[kk*8 + lc], bl1 = rl[kk*8 + lc + 4];
            mma_tf32(h0,h1,h2,h3, ahi[kk][0],ahi[kk][1],ahi[kk][2],ahi[kk][3], bh0,bh1);
            mma_tf32(m0a,m1a,m2a,m3a, ahi[kk][0],ahi[kk][1],ahi[kk][2],ahi[kk][3], bl0,bl1);
            mma_tf32(l0,l1,l2,l3, alo[kk][0],alo[kk][1],alo[kk][2],alo[kk][3], bh0,bh1);
        }
        float c0 = h0 + (m0a + l0);
        float c1 = h1 + (m1a + l1);
        float c2 = h2 + (m2a + l2);
        float c3 = h3 + (m3a + l3);
        float p0 = fmaxf(c0, c1);                 // channel m0+lr
        float p1 = fmaxf(c2, c3);                 // channel m0+8+lr
        p0 = fmaxf(p0, __shfl_xor_sync(0xFFFFFFFFu, p0, 1));
        p0 = fmaxf(p0, __shfl_xor_sync(0xFFFFFFFFu, p0, 2));
        p1 = fmaxf(p1, __shfl_xor_sync(0xFFFFFFFFu, p1, 1));
        p1 = fmaxf(p1, __shfl_xor_sync(0xFFFFFFFFu, p1, 2));
        if (nt & 1) {
            if (lc == 0) {
                int n = n0blk + sq*4 + (nt >> 1);
                out[((size_t)(b*CH + m0+lr  ))*NPTS + n] = fmaxf(prev0, p0);
                out[((size_t)(b*CH + m0+8+lr))*NPTS + n] = fmaxf(prev1, p1);
            }
        } else {
            prev0 = p0; prev1 = p1;
        }
    }
}

// ---------------- launch ----------------
extern "C" void kernel_launch(void* const* d_in, const int* in_sizes, int n_in,
                              void* d_out, int out_size) {
    const float* xyz   = (const float*)d_in[0];
    const float* w1    = (const float*)d_in[1];
    const float* b1    = (const float*)d_in[2];
    const float* w2    = (const float*)d_in[3];
    const float* b2    = (const float*)d_in[4];
    const float* gamma = (const float*)d_in[5];
    const float* beta  = (const float*)d_in[6];
    float* out = (float*)d_out;
    (void)in_sizes; (void)n_in; (void)out_size;

    const int smemMM = (2*SAMP*GPAD + CH*CH) * 4;   // 155648 B

    cudaFuncSetAttribute(k1_knn, cudaFuncAttributeMaxDynamicSharedMemorySize, 65536);
    cudaFuncSetAttribute(k3_h1,  cudaFuncAttributeMaxDynamicSharedMemorySize, smemMM);
    cudaFuncSetAttribute(k4_out, cudaFuncAttributeMaxDynamicSharedMemorySize, smemMM);

    k0_init<<<1, 256>>>();
    k1_knn<<<128, 256, 65536>>>(xyz);
    k2_fold0<<<1, 64>>>(w1, b1, gamma, beta);
    k3_h1<<<NBLK, 512, smemMM>>>(w2, b2);
    k3b_fold1<<<1, 64>>>(gamma, beta);
    k4_out<<<NBLK, 512, smemMM>>>(w2, b2, out);
}

// round 15
// speedup vs baseline: 1.1861x; 1.1861x over previous
#include <cuda_runtime.h>
#include <math.h>
#include <stdint.h>

#define BATCH 8
#define NPTS  4096
#define KNN   16
#define CH    64
#define NTILE 16
#define SAMP  256            // NTILE * KNN samples per tile block
#define NBLK  2048           // BATCH * (NPTS / NTILE)
#define GPAD  68             // padded row length (floats) for [s][c] smem tiles

// ---------------- device scratch (no allocations allowed) ----------------
__device__ float  g_rel[BATCH * NPTS * KNN * 3];        // 6.3 MB relative vectors
__device__ float  g_h1[(size_t)NBLK * SAMP * CH];       // 134 MB h1, layout [block][s][o]
__device__ double g_mom[9];                             // rel moments
__device__ float  g_w1f[CH * 3];                        // BN0-folded w1
__device__ float  g_b1f[CH];
__device__ double g_s1[CH];                             // sum h1 per channel
__device__ double g_ss1[CH];                            // sum h1^2 per channel
__device__ float  g_a1[CH];                             // BN1 scale
__device__ float  g_c1[CH];                             // BN1 shift

// ---------------- tf32 helpers ----------------
__device__ __forceinline__ uint32_t f2tf32(float x) {
    uint32_t r;
    asm("cvt.rna.tf32.f32 %0, %1;" : "=r"(r) : "f"(x));
    return r;
}
__device__ __forceinline__ float tf32r(float x) {      // round-to-tf32, keep as f32 bits
    return __uint_as_float(f2tf32(x));
}
__device__ __forceinline__ void tf32_split(float x, uint32_t& hi, uint32_t& lo) {
    hi = f2tf32(x);
    float rem = x - __uint_as_float(hi);
    lo = f2tf32(rem);
}
__device__ __forceinline__ void mma_tf32(float& c0, float& c1, float& c2, float& c3,
                                         uint32_t a0, uint32_t a1, uint32_t a2, uint32_t a3,
                                         uint32_t b0, uint32_t b1) {
    asm("mma.sync.aligned.m16n8k8.row.col.f32.tf32.tf32.f32 "
        "{%0,%1,%2,%3}, {%4,%5,%6,%7}, {%8,%9}, {%0,%1,%2,%3};"
        : "+f"(c0), "+f"(c1), "+f"(c2), "+f"(c3)
        : "r"(a0), "r"(a1), "r"(a2), "r"(a3), "r"(b0), "r"(b1));
}

// ---------------- K0: zero the cross-launch accumulators ----------------
__global__ void k0_init() {
    int t = threadIdx.x;
    if (t < 9)  g_mom[t] = 0.0;
    if (t < CH) { g_s1[t] = 0.0; g_ss1[t] = 0.0; }
}

// ---------------- K1: KNN (ranks 2..17 by LARGEST distance) + rel + rel moments ----
__global__ __launch_bounds__(256) void k1_knn(const float* __restrict__ xyz) {
    extern __shared__ float4 pts[];      // 4096 x (x,y,z,|p|^2) = 64 KB
    __shared__ float sacc[9];
    const int t    = threadIdx.x;
    const int b    = blockIdx.x >> 4;
    const int tile = blockIdx.x & 15;
    const float* xb = xyz + (size_t)b * 3 * NPTS;
    for (int n = t; n < NPTS; n += 256) {
        float x = xb[n], y = xb[NPTS + n], z = xb[2 * NPTS + n];
        pts[n] = make_float4(x, y, z, fmaf(x, x, fmaf(y, y, z * z)));
    }
    if (t < 9) sacc[t] = 0.0f;
    __syncthreads();

    const int i = tile * 256 + t;
    const float4 q = pts[i];

    float bd[17]; int bi[17];
    #pragma unroll
    for (int u = 0; u < 17; ++u) { bd[u] = -1e30f; bi[u] = 0; }
    float cmin = -1e30f; int cpos = 0;

    #pragma unroll 4
    for (int j = 0; j < NPTS; ++j) {
        float4 p = pts[j];
        float dt = fmaf(q.x, p.x, fmaf(q.y, p.y, q.z * p.z));
        float d  = q.w + p.w - 2.0f * dt;
        if (d > cmin) {            // strict >: ties keep earlier (lower) index, like jax top_k
            bd[cpos] = d; bi[cpos] = j;
            cmin = bd[0]; cpos = 0;
            #pragma unroll
            for (int u = 1; u < 17; ++u)
                if (bd[u] < cmin) { cmin = bd[u]; cpos = u; }
        }
    }

    float mval = bd[0]; int mpos = 0;
    #pragma unroll
    for (int u = 1; u < 17; ++u)
        if (bd[u] > mval || (bd[u] == mval && bi[u] < bi[mpos])) { mval = bd[u]; mpos = u; }

    float sx=0,sy=0,sz=0,sxx=0,sxy=0,sxz=0,syy=0,syz=0,szz=0;
    float* outr = g_rel + (size_t)(b * NPTS + i) * (KNN * 3);
    int kk = 0;
    #pragma unroll
    for (int u = 0; u < 17; ++u) {
        if (u == mpos) continue;
        float4 p = pts[bi[u]];
        float rx = p.x - q.x, ry = p.y - q.y, rz = p.z - q.z;
        outr[kk*3+0] = rx; outr[kk*3+1] = ry; outr[kk*3+2] = rz;
        ++kk;
        sx += rx; sy += ry; sz += rz;
        sxx = fmaf(rx,rx,sxx); sxy = fmaf(rx,ry,sxy); sxz = fmaf(rx,rz,sxz);
        syy = fmaf(ry,ry,syy); syz = fmaf(ry,rz,syz); szz = fmaf(rz,rz,szz);
    }
    atomicAdd(&sacc[0],sx);  atomicAdd(&sacc[1],sy);  atomicAdd(&sacc[2],sz);
    atomicAdd(&sacc[3],sxx); atomicAdd(&sacc[4],sxy); atomicAdd(&sacc[5],sxz);
    atomicAdd(&sacc[6],syy); atomicAdd(&sacc[7],syz); atomicAdd(&sacc[8],szz);
    __syncthreads();
    if (t < 9) atomicAdd(&g_mom[t], (double)sacc[t]);
}

// ---------------- K2: fold block-0 BN into w1 (exact, from rel moments) ----------------
__global__ void k2_fold0(const float* __restrict__ w1, const float* __restrict__ b1,
                         const float* __restrict__ gamma, const float* __restrict__ beta) {
    int o = threadIdx.x;
    if (o >= CH) return;
    double inv = 1.0 / ((double)BATCH * NPTS * KNN);
    double m0=g_mom[0]*inv, m1=g_mom[1]*inv, m2=g_mom[2]*inv;
    double Mxx=g_mom[3]*inv, Mxy=g_mom[4]*inv, Mxz=g_mom[5]*inv;
    double Myy=g_mom[6]*inv, Myz=g_mom[7]*inv, Mzz=g_mom[8]*inv;
    double wx=w1[o*3+0], wy=w1[o*3+1], wz=w1[o*3+2], bb=b1[o];
    double wm = wx*m0 + wy*m1 + wz*m2;
    double mu = wm + bb;
    double e2 = wx*wx*Mxx + wy*wy*Myy + wz*wz*Mzz
              + 2.0*(wx*wy*Mxy + wx*wz*Mxz + wy*wz*Myz)
              + 2.0*bb*wm + bb*bb;
    double var = e2 - mu*mu;
    double a = (double)gamma[o] / sqrt(var + 1e-5);
    g_w1f[o*3+0]=(float)(a*wx); g_w1f[o*3+1]=(float)(a*wy); g_w1f[o*3+2]=(float)(a*wz);
    g_b1f[o]=(float)(a*(bb-mu) + (double)beta[o]);
}

// ---------------- K3: g1 = relu(BN0(w1 rel)); h1 = w2 g1 + b2 (2-pass tf32 MMA) ----
__global__ __launch_bounds__(256, 2) void k3_h1(const float* __restrict__ w2, const float* __restrict__ b2) {
    extern __shared__ float sm3[];
    float* g1s = sm3;                  // [256][GPAD] tf32-rounded g1 (69632 B)
    float* w2s = sm3 + SAMP*GPAD;      // [64][64] plain (16384 B)
    __shared__ float w1fs[CH*3], b1fs[CH], b2s[CH], sh1[CH], sq1[CH];
    const int t  = threadIdx.x;
    const int b  = blockIdx.x >> 8;
    const int n0blk = (blockIdx.x & 255) * NTILE;

    for (int idx = t; idx < CH*CH; idx += 256) w2s[idx] = w2[idx];
    if (t < CH*3) w1fs[t] = g_w1f[t];
    if (t < CH) { b1fs[t] = g_b1f[t]; b2s[t] = b2[t]; sh1[t]=0.f; sq1[t]=0.f; }
    __syncthreads();

    {   // stage 1: g1 for this tile, rounded to tf32 once; sample s = t
        const int nl = t >> 4, k = t & 15;
        const float* r = g_rel + (size_t)((b*NPTS + n0blk + nl)*KNN + k)*3;
        float rx=r[0], ry=r[1], rz=r[2];
        float* row = g1s + t*GPAD;
        #pragma unroll
        for (int o = 0; o < CH; o += 4) {
            float4 v;
            v.x = tf32r(fmaxf(fmaf(w1fs[(o+0)*3], rx, fmaf(w1fs[(o+0)*3+1], ry, fmaf(w1fs[(o+0)*3+2], rz, b1fs[o+0]))), 0.f));
            v.y = tf32r(fmaxf(fmaf(w1fs[(o+1)*3], rx, fmaf(w1fs[(o+1)*3+1], ry, fmaf(w1fs[(o+1)*3+2], rz, b1fs[o+1]))), 0.f));
            v.z = tf32r(fmaxf(fmaf(w1fs[(o+2)*3], rx, fmaf(w1fs[(o+2)*3+1], ry, fmaf(w1fs[(o+2)*3+2], rz, b1fs[o+2]))), 0.f));
            v.w = tf32r(fmaxf(fmaf(w1fs[(o+3)*3], rx, fmaf(w1fs[(o+3)*3+1], ry, fmaf(w1fs[(o+3)*3+2], rz, b1fs[o+3]))), 0.f));
            *(float4*)(row + o) = v;
        }
    }
    __syncthreads();

    // mma stage: warp -> 16 out rows (m0) x 128 samples (shalf)
    const int warp = t >> 5, lane = t & 31, lr = lane >> 2, lc = lane & 3;
    const int m0 = (warp & 3) * 16, shalf = warp >> 2;

    // Load W frags (hi+lo split) once: A row-major 16x8 per k-step
    uint32_t ahi[8][4], alo[8][4];
    #pragma unroll
    for (int kk = 0; kk < 8; ++kk) {
        int c0i = kk*8 + lc;
        tf32_split(w2s[(m0+lr  )*CH + c0i    ], ahi[kk][0], alo[kk][0]);
        tf32_split(w2s[(m0+lr+8)*CH + c0i    ], ahi[kk][1], alo[kk][1]);
        tf32_split(w2s[(m0+lr  )*CH + c0i + 4], ahi[kk][2], alo[kk][2]);
        tf32_split(w2s[(m0+lr+8)*CH + c0i + 4], ahi[kk][3], alo[kk][3]);
    }

    float bias0 = b2s[m0+lr], bias1 = b2s[m0+8+lr];
    float sum0=0.f, ssq0=0.f, sum1=0.f, ssq1=0.f;
    float* hb = g_h1 + (size_t)blockIdx.x * (SAMP*CH);

    for (int nt = 0; nt < 16; ++nt) {
        const int n0 = shalf*128 + nt*8;
        float h0=bias0,h1=bias0,h2=bias1,h3=bias1;   // Ahi*Bhi (+bias)
        float l0=0,l1=0,l2=0,l3=0;                   // Alo*Bhi
        const uint32_t* grow = (const uint32_t*)(g1s + (n0+lr)*GPAD);
        #pragma unroll
        for (int kk = 0; kk < 8; ++kk) {
            uint32_t bh0 = grow[kk*8 + lc];
            uint32_t bh1 = grow[kk*8 + lc + 4];
            mma_tf32(h0,h1,h2,h3, ahi[kk][0],ahi[kk][1],ahi[kk][2],ahi[kk][3], bh0,bh1);
            mma_tf32(l0,l1,l2,l3, alo[kk][0],alo[kk][1],alo[kk][2],alo[kk][3], bh0,bh1);
        }
        float c0 = h0 + l0;
        float c1 = h1 + l1;
        float c2 = h2 + l2;
        float c3 = h3 + l3;
        // acc layout: c0:(o=m0+lr, s=n0+2lc) c1:s+1  c2:(o=m0+8+lr, s=n0+2lc) c3:s+1
        const int s0 = n0 + 2*lc;
        hb[(s0  )*CH + m0+lr  ] = c0;
        hb[(s0+1)*CH + m0+lr  ] = c1;
        hb[(s0  )*CH + m0+8+lr] = c2;
        hb[(s0+1)*CH + m0+8+lr] = c3;
        sum0 += c0 + c1;  ssq0 = fmaf(c0,c0, fmaf(c1,c1, ssq0));
        sum1 += c2 + c3;  ssq1 = fmaf(c2,c2, fmaf(c3,c3, ssq1));
    }
    // reduce stats across the 4 lanes sharing channels (same lr)
    sum0 += __shfl_xor_sync(0xFFFFFFFFu, sum0, 1); sum0 += __shfl_xor_sync(0xFFFFFFFFu, sum0, 2);
    ssq0 += __shfl_xor_sync(0xFFFFFFFFu, ssq0, 1); ssq0 += __shfl_xor_sync(0xFFFFFFFFu, ssq0, 2);
    sum1 += __shfl_xor_sync(0xFFFFFFFFu, sum1, 1); sum1 += __shfl_xor_sync(0xFFFFFFFFu, sum1, 2);
    ssq1 += __shfl_xor_sync(0xFFFFFFFFu, ssq1, 1); ssq1 += __shfl_xor_sync(0xFFFFFFFFu, ssq1, 2);
    if (lc == 0) {
        atomicAdd(&sh1[m0+lr  ], sum0); atomicAdd(&sq1[m0+lr  ], ssq0);
        atomicAdd(&sh1[m0+8+lr], sum1); atomicAdd(&sq1[m0+8+lr], ssq1);
    }
    __syncthreads();
    if (t < CH) { atomicAdd(&g_s1[t], (double)sh1[t]); atomicAdd(&g_ss1[t], (double)sq1[t]); }
}

// ---------------- K3b: finalize block-1 BN affine ----------------
__global__ void k3b_fold1(const float* __restrict__ gamma, const float* __restrict__ beta) {
    int o = threadIdx.x;
    if (o >= CH) return;
    double inv = 1.0 / ((double)BATCH * NPTS * KNN);
    double mu  = g_s1[o] * inv;
    double var = g_ss1[o] * inv - mu*mu;
    double a = (double)gamma[o] / sqrt(var + 1e-5);
    g_a1[o] = (float)a;
    g_c1[o] = (float)((double)beta[o] - a*mu);
}

// ---------------- K4: g2 = relu(BN1(h1)); h2 = w2 g2 + b2; max over k -> out ----------------
__global__ __launch_bounds__(256, 2) void k4_out(const float* __restrict__ w2, const float* __restrict__ b2,
                                                  float* __restrict__ out) {
    extern __shared__ float sm4[];
    float* g2s = sm4;                  // [256][GPAD] tf32-rounded g2
    float* w2s = sm4 + SAMP*GPAD;      // [64][64]
    __shared__ __align__(16) float a1s[CH];
    __shared__ __align__(16) float c1s[CH];
    __shared__ float b2s[CH];
    const int t  = threadIdx.x;
    const int b  = blockIdx.x >> 8;
    const int n0blk = (blockIdx.x & 255) * NTILE;

    for (int idx = t; idx < CH*CH; idx += 256) w2s[idx] = w2[idx];
    if (t < CH) { a1s[t]=g_a1[t]; c1s[t]=g_c1[t]; b2s[t]=b2[t]; }
    __syncthreads();

    // BN + relu + tf32-round -> padded [s][c] tile (h1 stored [s][o] -> coalesced)
    const float* hb = g_h1 + (size_t)blockIdx.x * (SAMP*CH);
    for (int idx = t*4; idx < SAMP*CH; idx += 256*4) {
        float4 v = *(const float4*)(hb + idx);
        int o = idx & 63, s = idx >> 6;
        float4 a = *(const float4*)(a1s + o);
        float4 c = *(const float4*)(c1s + o);
        v.x = tf32r(fmaxf(fmaf(a.x, v.x, c.x), 0.f));
        v.y = tf32r(fmaxf(fmaf(a.y, v.y, c.y), 0.f));
        v.z = tf32r(fmaxf(fmaf(a.z, v.z, c.z), 0.f));
        v.w = tf32r(fmaxf(fmaf(a.w, v.w, c.w), 0.f));
        *(float4*)(g2s + s*GPAD + o) = v;
    }
    __syncthreads();

    const int warp = t >> 5, lane = t & 31, lr = lane >> 2, lc = lane & 3;
    const int m0 = (warp & 3) * 16, shalf = warp >> 2;

    uint32_t ahi[8][4], alo[8][4];
    #pragma unroll
    for (int kk = 0; kk < 8; ++kk) {
        int c0i = kk*8 + lc;
        tf32_split(w2s[(m0+lr  )*CH + c0i    ], ahi[kk][0], alo[kk][0]);
        tf32_split(w2s[(m0+lr+8)*CH + c0i    ], ahi[kk][1], alo[kk][1]);
        tf32_split(w2s[(m0+lr  )*CH + c0i + 4], ahi[kk][2], alo[kk][2]);
        tf32_split(w2s[(m0+lr+8)*CH + c0i + 4], ahi[kk][3], alo[kk][3]);
    }

    float bias0 = b2s[m0+lr], bias1 = b2s[m0+8+lr];
    float prev0 = 0.f, prev1 = 0.f;

    for (int nt = 0; nt < 16; ++nt) {
        const int n0 = shalf*128 + nt*8;
        float h0=bias0,h1=bias0,h2=bias1,h3=bias1;
        float l0=0,l1=0,l2=0,l3=0;
        const uint32_t* grow = (const uint32_t*)(g2s + (n0+lr)*GPAD);
        #pragma unroll
        for (int kk = 0; kk < 8; ++kk) {
            uint32_t bh0 = grow[kk*8 + lc];
            uint32_t bh1 = grow[kk*8 + lc + 4];
            mma_tf32(h0,h1,h2,h3, ahi[kk][0],ahi[kk][1],ahi[kk][2],ahi[kk][3], bh0,bh1);
            mma_tf32(l0,l1,l2,l3, alo[kk][0],alo[kk][1],alo[kk][2],alo[kk][3], bh0,bh1);
        }
        float c0 = h0 + l0;
        float c1 = h1 + l1;
        float c2 = h2 + l2;
        float c3 = h3 + l3;
        // max over this n-tile's samples: lane holds s=n0+2lc, +1
        float p0 = fmaxf(c0, c1);                 // channel m0+lr
        float p1 = fmaxf(c2, c3);                 // channel m0+8+lr
        p0 = fmaxf(p0, __shfl_xor_sync(0xFFFFFFFFu, p0, 1));
        p0 = fmaxf(p0, __shfl_xor_sync(0xFFFFFFFFu, p0, 2));
        p1 = fmaxf(p1, __shfl_xor_sync(0xFFFFFFFFu, p1, 1));
        p1 = fmaxf(p1, __shfl_xor_sync(0xFFFFFFFFu, p1, 2));
        if (nt & 1) {
            // combine k-halves -> full point; point = shalf*8 + nt/2
            if (lc == 0) {
                int n = n0blk + shalf*8 + (nt >> 1);
                out[((size_t)(b*CH + m0+lr  ))*NPTS + n] = fmaxf(prev0, p0);
                out[((size_t)(b*CH + m0+8+lr))*NPTS + n] = fmaxf(prev1, p1);
            }
        } else {
            prev0 = p0; prev1 = p1;
        }
    }
}

// ---------------- launch ----------------
extern "C" void kernel_launch(void* const* d_in, const int* in_sizes, int n_in,
                              void* d_out, int out_size) {
    const float* xyz   = (const float*)d_in[0];
    const float* w1    = (const float*)d_in[1];
    const float* b1    = (const float*)d_in[2];
    const float* w2    = (const float*)d_in[3];
    const float* b2    = (const float*)d_in[4];
    const float* gamma = (const float*)d_in[5];
    const float* beta  = (const float*)d_in[6];
    float* out = (float*)d_out;
    (void)in_sizes; (void)n_in; (void)out_size;

    const int smemMM = (SAMP*GPAD + CH*CH) * 4;   // 86016 B

    cudaFuncSetAttribute(k1_knn, cudaFuncAttributeMaxDynamicSharedMemorySize, 65536);
    cudaFuncSetAttribute(k3_h1,  cudaFuncAttributeMaxDynamicSharedMemorySize, smemMM);
    cudaFuncSetAttribute(k4_out, cudaFuncAttributeMaxDynamicSharedMemorySize, smemMM);

    k0_init<<<1, 256>>>();
    k1_knn<<<128, 256, 65536>>>(xyz);
    k2_fold0<<<1, 64>>>(w1, b1, gamma, beta);
    k3_h1<<<NBLK, 256, smemMM>>>(w2, b2);
    k3b_fold1<<<1, 64>>>(gamma, beta);
    k4_out<<<NBLK, 256, smemMM>>>(w2, b2, out);
}